// round 16
// baseline (speedup 1.0000x reference)
#include <cuda_runtime.h>
#include <math.h>

#define NB 8
#define NM 64
#define NP (NM / 2)                  // 32 box pairs
#define NA 49104
#define NC 80
#define THREADS 256
#define NA_TILES 192                 // ceil(NA / 256)
#define NAB (NA_TILES * NB)          // 1536 assign blocks
#define NSPI 148                     // stream blocks per image
#define NSB (NSPI * NB)              // 1184 stream blocks
#define TOTB (NAB + NSB)             // 2720
#define VEC (NA * (NC / 4))          // float4s per image = 982080
#define SSTRIDE (NSPI * THREADS)
#define KNEG (-0.75f * 0.69314718055994530942f)   // -0.75*ln2 (lg2-domain scale)
#define PMAX (1.0f - 1e-4f)

// global accumulators (zero at module load; last block resets for next replay)
__device__ double       g_cls[NB];
__device__ double       g_reg[NB];
__device__ int          g_npos[NB];
__device__ unsigned int g_done = 0;

__device__ __forceinline__ void commit(float c, float r, int p, int b,
                                       float* s_c, float* s_r, int* s_p,
                                       float* __restrict__ out) {
    #pragma unroll
    for (int o = 16; o; o >>= 1) {
        c += __shfl_down_sync(0xFFFFFFFFu, c, o);
        r += __shfl_down_sync(0xFFFFFFFFu, r, o);
        p += __shfl_down_sync(0xFFFFFFFFu, p, o);
    }
    const int wid = threadIdx.x >> 5, lid = threadIdx.x & 31;
    if (lid == 0) { s_c[wid] = c; s_r[wid] = r; s_p[wid] = p; }
    __syncthreads();
    if (wid == 0) {
        const int nw = THREADS / 32;
        c = (lid < nw) ? s_c[lid] : 0.0f;
        r = (lid < nw) ? s_r[lid] : 0.0f;
        p = (lid < nw) ? s_p[lid] : 0;
        #pragma unroll
        for (int o = 16; o; o >>= 1) {
            c += __shfl_down_sync(0xFFFFFFFFu, c, o);
            r += __shfl_down_sync(0xFFFFFFFFu, r, o);
            p += __shfl_down_sync(0xFFFFFFFFu, p, o);
        }
        if (lid == 0) {
            atomicAdd(&g_cls[b], (double)c);
            if (r != 0.0f) atomicAdd(&g_reg[b], (double)r);
            if (p)         atomicAdd(&g_npos[b], p);
            __threadfence();
            unsigned int ticket = atomicAdd(&g_done, 1u);
            if (ticket == (unsigned int)(TOTB - 1)) {
                double cs = 0.0, rs = 0.0;
                #pragma unroll
                for (int i = 0; i < NB; i++) {
                    double gc = atomicAdd(&g_cls[i], 0.0);   // atomic read
                    double gr = atomicAdd(&g_reg[i], 0.0);
                    int    np = atomicAdd(&g_npos[i], 0);
                    double den = (double)(np > 1 ? np : 1);
                    cs += gc / den;
                    rs += (np > 0) ? (gr / (4.0 * den)) : 0.0;
                    g_cls[i] = 0.0; g_reg[i] = 0.0; g_npos[i] = 0;
                }
                out[0] = (float)(cs / (double)NB);
                out[1] = (float)(rs / (double)NB * 50.0);
                __threadfence();
                g_done = 0;
            }
        }
    }
}

__global__ __launch_bounds__(THREADS)
void fl_kernel(const float* __restrict__ boxes,      // [B,M,4] (x1,y1,x2,y2)
               const int*   __restrict__ labels,     // [B,M]
               const float* __restrict__ anchors,    // [1,A,4] (y1,x1,y2,x2)
               const float* __restrict__ cls,        // [B,A,C]
               const float* __restrict__ reg,        // [B,A,4]
               float*       __restrict__ out)        // [2]
{
    __shared__ float4 s_box[NM];
    __shared__ int    s_lab[NM];
    __shared__ float4 s_zx[NP];   // (z_e, z_o, -x_e, -x_o)
    __shared__ float4 s_wy[NP];   // (w_e, w_o, -y_e, -y_o)
    __shared__ float2 s_ba[NP];   // (barea_e, barea_o)
    __shared__ float  s_c[THREADS / 32];
    __shared__ float  s_r[THREADS / 32];
    __shared__ int    s_p[THREADS / 32];

    const int gid = blockIdx.x;
    const int t   = threadIdx.x;

    // interleave roles so assign (issue-bound) and stream (DRAM-bound) co-reside
    int role, idx;
    if (gid < 2 * NSB) { role = gid & 1; idx = gid >> 1; }
    else               { role = 0;       idx = NSB + (gid - 2 * NSB); }

    if (role == 1) {
        // ===== STREAM: negative focal term, lg2 domain, upper clamp only =====
        const int b   = idx / NSPI;
        const int blk = idx - b * NSPI;
        const float4* __restrict__ cp = (const float4*)(cls + (size_t)b * NA * NC);
        const int tid = blk * THREADS + t;

        float s0 = 0.0f, s1 = 0.0f, s2 = 0.0f, s3 = 0.0f;
        #pragma unroll 8
        for (int i = tid; i < VEC; i += SSTRIDE) {
            float4 v = cp[i];
            float p0 = fminf(v.x, PMAX);           // lower clamp dropped: |err| < 1e-12/elem
            float p1 = fminf(v.y, PMAX);
            float p2 = fminf(v.z, PMAX);
            float p3 = fminf(v.w, PMAX);
            s0 = fmaf(p0 * p0, __log2f(1.0f - p0), s0);
            s1 = fmaf(p1 * p1, __log2f(1.0f - p1), s1);
            s2 = fmaf(p2 * p2, __log2f(1.0f - p2), s2);
            s3 = fmaf(p3 * p3, __log2f(1.0f - p3), s3);
        }
        float csum = KNEG * ((s0 + s1) + (s2 + s3));
        commit(csum, 0.0f, 0, b, s_c, s_r, s_p, out);
        return;
    }

    // ===== ASSIGN: branch-free mantissa-encoded argmax on r = I/S =====
    const int b    = idx / NA_TILES;
    const int tile = idx - b * NA_TILES;

    if (t < NM) {
        float4 bx = ((const float4*)boxes)[b * NM + t];
        int lab   = labels[b * NM + t];
        if (lab == 0)                            // degenerate: inter clamps to 0
            bx = make_float4(3e9f, 3e9f, -3e9f, -3e9f);
        s_box[t] = bx;
        s_lab[t] = lab;
    }
    if (t < NP) {                                // pack pair q = t (boxes 2q, 2q+1)
        float4 e = ((const float4*)boxes)[b * NM + 2 * t];
        float4 o = ((const float4*)boxes)[b * NM + 2 * t + 1];
        int le = labels[b * NM + 2 * t], lo = labels[b * NM + 2 * t + 1];
        float bae, bao;
        if (le == 0) { e = make_float4(3e9f, 3e9f, -3e9f, -3e9f); bae = 0.0f; }
        else bae = (e.z - e.x) * (e.w - e.y);
        if (lo == 0) { o = make_float4(3e9f, 3e9f, -3e9f, -3e9f); bao = 0.0f; }
        else bao = (o.z - o.x) * (o.w - o.y);
        s_zx[t] = make_float4(e.z, o.z, -e.x, -o.x);
        s_wy[t] = make_float4(e.w, o.w, -e.y, -o.y);
        s_ba[t] = make_float2(bae, bao);
    }
    __syncthreads();

    const int a = tile * THREADS + t;
    float my_reg = 0.0f, my_cls = 0.0f;
    int   my_pos = 0;

    if (a < NA) {
        float4 an = ((const float4*)anchors)[a];   // y1,x1,y2,x2
        const float ay1 = an.x, ax1 = an.y, ay2 = an.z, ax2 = an.w;
        const float nax1 = -ax1, nay1 = -ay1;
        const float a_area = (ay2 - ay1) * (ax2 - ax1);

        // two chains (even/odd boxes); chain update = single FMNMX on an
        // index-stamped ratio: enc = (bits(r) & ~31) | (31-q).
        // Perturbs r by <2^-18 rel (winner re-verified exactly below);
        // (31-q) tie-break keeps first-max semantics within each chain.
        float be0 = 0.0f, be1 = 0.0f;              // r >= 0 always
        #pragma unroll 8
        for (int q = 0; q < NP; q++) {
            float4 zx = s_zx[q];                 // z_e,z_o,-x_e,-x_o
            float4 wy = s_wy[q];                 // w_e,w_o,-y_e,-y_o
            float2 ba = s_ba[q];
            // iw = min(ax2,z) + min(-ax1,-x) == min(ax2,z) - max(ax1,x)  (exact)
            float iw0 = fminf(ax2, zx.x) + fminf(nax1, zx.z);
            float iw1 = fminf(ax2, zx.y) + fminf(nax1, zx.w);
            float ih0 = fminf(ay2, wy.x) + fminf(nay1, wy.z);
            float ih1 = fminf(ay2, wy.y) + fminf(nay1, wy.w);
            float I0 = fmaxf(iw0, 0.0f) * fmaxf(ih0, 0.0f);
            float I1 = fmaxf(iw1, 0.0f) * fmaxf(ih1, 0.0f);
            float r0 = __fdividef(I0, a_area + ba.x);   // MUFU.RCP + FMUL
            float r1 = __fdividef(I1, a_area + ba.y);
            float e0 = __int_as_float((__float_as_int(r0) & ~31) | (31 - q));
            float e1 = __int_as_float((__float_as_int(r1) & ~31) | (31 - q));
            be0 = fmaxf(be0, e0);
            be1 = fmaxf(be1, e1);
        }
        // decode winners; odd chain wins only with strictly larger ratio bits
        unsigned ib0 = __float_as_uint(be0), ib1 = __float_as_uint(be1);
        int bidx;
        if ((ib1 & ~31u) > (ib0 & ~31u)) bidx = 2 * (31 - (int)(ib1 & 31u)) + 1;
        else                             bidx = 2 * (31 - (int)(ib0 & 31u));

        // winner: recompute IoU EXACTLY as the reference does
        float4 ab = s_box[bidx];
        float iwx = fminf(ax2, ab.z) - fmaxf(ax1, ab.x);
        float ihx = fminf(ay2, ab.w) - fmaxf(ay1, ab.y);
        iwx = fmaxf(iwx, 0.0f); ihx = fmaxf(ihx, 0.0f);
        float inter = iwx * ihx;
        float barea = (ab.z - ab.x) * (ab.w - ab.y);
        float ua = fmaxf(a_area + barea - inter, 1e-8f);
        float iou_max = inter / ua;                // IEEE divide, once per anchor

        float  bw = ab.z - ab.x, bh = ab.w - ab.y;
        bool   big = (bw * bh) > 100.0f;
        bool   pos = big ? (iou_max >= 0.5f) : (iou_max >= 0.15f);

        if (pos) {
            my_pos = 1;
            float gcx = ab.x + 0.5f * bw, gcy = ab.y + 0.5f * bh;
            float gw = fmaxf(bw, 1.0f), gh = fmaxf(bh, 1.0f);
            float aw = ax2 - ax1, ah = ay2 - ay1;
            float acx = ax1 + 0.5f * aw, acy = ay1 + 0.5f * ah;
            float tt0 = (gcy - acy) / ah;
            float tt1 = (gcx - acx) / aw;
            float tt2 = logf(gh / ah);
            float tt3 = logf(gw / aw);
            float4 r = ((const float4*)reg)[(size_t)b * NA + a];
            float d;
            d = fabsf(tt0 - r.x); my_reg += (d <= 1.0f/9.0f) ? 4.5f*d*d : d - 0.5f/9.0f;
            d = fabsf(tt1 - r.y); my_reg += (d <= 1.0f/9.0f) ? 4.5f*d*d : d - 0.5f/9.0f;
            d = fabsf(tt2 - r.z); my_reg += (d <= 1.0f/9.0f) ? 4.5f*d*d : d - 0.5f/9.0f;
            d = fabsf(tt3 - r.w); my_reg += (d <= 1.0f/9.0f) ? 4.5f*d*d : d - 0.5f/9.0f;

            // cls correction for the target class:
            //  + reference positive term (full clamp)
            //  - EXACTLY the neg term the stream added (upper clamp only)
            int al = s_lab[bidx] - 1;              // in [0, NC)
            float v = cls[((size_t)b * NA + a) * NC + al];
            float ps = fminf(v, PMAX);             // stream's p (upper clamp only)
            float neg_term = KNEG * (ps * ps) * __log2f(1.0f - ps);
            float p = fminf(fmaxf(v, 1e-4f), PMAX);
            float om = 1.0f - p;
            my_cls = 0.25f * om * om * (-__logf(p)) - neg_term;
        }
    }
    commit(my_cls, my_reg, my_pos, b, s_c, s_r, s_p, out);
}

extern "C" void kernel_launch(void* const* d_in, const int* in_sizes, int n_in,
                              void* d_out, int out_size) {
    const float* boxes   = (const float*)d_in[0];
    const int*   labels  = (const int*)  d_in[1];
    const float* anchors = (const float*)d_in[2];
    const float* cls     = (const float*)d_in[3];
    const float* reg     = (const float*)d_in[4];
    float* out = (float*)d_out;

    fl_kernel<<<TOTB, THREADS>>>(boxes, labels, anchors, cls, reg, out);
}

// round 17
// speedup vs baseline: 1.0371x; 1.0371x over previous
#include <cuda_runtime.h>
#include <math.h>

#define NB 8
#define NM 64
#define NP (NM / 2)                  // 32 box pairs
#define NA 49104
#define NC 80
#define THREADS 256
#define NA_TILES 192                 // ceil(NA / 256)
#define NAB (NA_TILES * NB)          // 1536 assign blocks
#define NSPI 148                     // stream blocks per image
#define NSB (NSPI * NB)              // 1184 stream blocks
#define TOTB (NAB + NSB)             // 2720
#define VEC (NA * (NC / 4))          // float4s per image = 982080
#define SSTRIDE (NSPI * THREADS)
#define KNEG (-0.75f * 0.69314718055994530942f)   // -0.75*ln2 (lg2-domain scale)

typedef unsigned long long u64;

// packed f32x2 ops available on sm_100a (min/max.f32x2 are NOT -- sm_103a only)
#define F2ADD(d, a, b)    asm("add.rn.f32x2 %0, %1, %2;"     : "=l"(d) : "l"(a), "l"(b))
#define F2MUL(d, a, b)    asm("mul.rn.f32x2 %0, %1, %2;"     : "=l"(d) : "l"(a), "l"(b))
#define F2FMA(d, a, b, c) asm("fma.rn.f32x2 %0, %1, %2, %3;" : "=l"(d) : "l"(a), "l"(b), "l"(c))
#define F2PK(d, lo, hi)   asm("mov.b64 %0, {%1, %2};"        : "=l"(d) : "f"(lo), "f"(hi))
#define F2UP(lo, hi, s)   asm("mov.b64 {%0, %1}, %2;"        : "=f"(lo), "=f"(hi) : "l"(s))

__device__ __forceinline__ u64 pk2c(float lo, float hi) {   // constexpr-ish pack
    return (u64)__float_as_uint(lo) | ((u64)__float_as_uint(hi) << 32);
}

// global accumulators (zero at module load; last block resets for next replay)
__device__ double       g_cls[NB];
__device__ double       g_reg[NB];
__device__ int          g_npos[NB];
__device__ unsigned int g_done = 0;

__device__ __forceinline__ void commit(float c, float r, int p, int b,
                                       float* s_c, float* s_r, int* s_p,
                                       float* __restrict__ out) {
    #pragma unroll
    for (int o = 16; o; o >>= 1) {
        c += __shfl_down_sync(0xFFFFFFFFu, c, o);
        r += __shfl_down_sync(0xFFFFFFFFu, r, o);
        p += __shfl_down_sync(0xFFFFFFFFu, p, o);
    }
    const int wid = threadIdx.x >> 5, lid = threadIdx.x & 31;
    if (lid == 0) { s_c[wid] = c; s_r[wid] = r; s_p[wid] = p; }
    __syncthreads();
    if (wid == 0) {
        const int nw = THREADS / 32;
        c = (lid < nw) ? s_c[lid] : 0.0f;
        r = (lid < nw) ? s_r[lid] : 0.0f;
        p = (lid < nw) ? s_p[lid] : 0;
        #pragma unroll
        for (int o = 16; o; o >>= 1) {
            c += __shfl_down_sync(0xFFFFFFFFu, c, o);
            r += __shfl_down_sync(0xFFFFFFFFu, r, o);
            p += __shfl_down_sync(0xFFFFFFFFu, p, o);
        }
        if (lid == 0) {
            atomicAdd(&g_cls[b], (double)c);
            if (r != 0.0f) atomicAdd(&g_reg[b], (double)r);
            if (p)         atomicAdd(&g_npos[b], p);
            __threadfence();
            unsigned int ticket = atomicAdd(&g_done, 1u);
            if (ticket == (unsigned int)(TOTB - 1)) {
                double cs = 0.0, rs = 0.0;
                #pragma unroll
                for (int i = 0; i < NB; i++) {
                    double gc = atomicAdd(&g_cls[i], 0.0);   // atomic read
                    double gr = atomicAdd(&g_reg[i], 0.0);
                    int    np = atomicAdd(&g_npos[i], 0);
                    double den = (double)(np > 1 ? np : 1);
                    cs += gc / den;
                    rs += (np > 0) ? (gr / (4.0 * den)) : 0.0;
                    g_cls[i] = 0.0; g_reg[i] = 0.0; g_npos[i] = 0;
                }
                out[0] = (float)(cs / (double)NB);
                out[1] = (float)(rs / (double)NB * 50.0);
                __threadfence();
                g_done = 0;
            }
        }
    }
}

__global__ __launch_bounds__(THREADS)
void fl_kernel(const float* __restrict__ boxes,      // [B,M,4] (x1,y1,x2,y2)
               const int*   __restrict__ labels,     // [B,M]
               const float* __restrict__ anchors,    // [1,A,4] (y1,x1,y2,x2)
               const float* __restrict__ cls,        // [B,A,C]
               const float* __restrict__ reg,        // [B,A,4]
               float*       __restrict__ out)        // [2]
{
    __shared__ float4 s_box[NM];
    __shared__ int    s_lab[NM];
    __shared__ float4 s_zx[NP];   // (z_e, z_o, -x_e, -x_o)
    __shared__ float4 s_wy[NP];   // (w_e, w_o, -y_e, -y_o)
    __shared__ u64    s_ba[NP];   // packed (barea_e, barea_o)
    __shared__ float  s_c[THREADS / 32];
    __shared__ float  s_r[THREADS / 32];
    __shared__ int    s_p[THREADS / 32];

    const int gid = blockIdx.x;
    const int t   = threadIdx.x;

    // interleave roles so assign (issue-bound) and stream (DRAM-bound) co-reside
    int role, idx;
    if (gid < 2 * NSB) { role = gid & 1; idx = gid >> 1; }
    else               { role = 0;       idx = NSB + (gid - 2 * NSB); }

    if (role == 1) {
        // ============ STREAM: negative focal term over [A,C], lg2 domain ============
        const int b   = idx / NSPI;
        const int blk = idx - b * NSPI;
        const float4* __restrict__ cp = (const float4*)(cls + (size_t)b * NA * NC);
        const int tid = blk * THREADS + t;

        const u64 one2  = pk2c(1.0f, 1.0f);
        const u64 none2 = pk2c(-1.0f, -1.0f);
        u64 acc01 = 0ull, acc23 = 0ull;          // packed (0.0, 0.0)
        #pragma unroll 4
        for (int i = tid; i < VEC; i += SSTRIDE) {
            float4 v = cp[i];
            float p0 = fminf(fmaxf(v.x, 1e-4f), 1.0f - 1e-4f);
            float p1 = fminf(fmaxf(v.y, 1e-4f), 1.0f - 1e-4f);
            float p2 = fminf(fmaxf(v.z, 1e-4f), 1.0f - 1e-4f);
            float p3 = fminf(fmaxf(v.w, 1e-4f), 1.0f - 1e-4f);
            u64 p01, p23, pp01, pp23, om01, om23, l01, l23;
            F2PK(p01, p0, p1); F2PK(p23, p2, p3);
            F2MUL(pp01, p01, p01);               // p^2
            F2MUL(pp23, p23, p23);
            F2FMA(om01, p01, none2, one2);       // 1 - p (exact, same as FADD)
            F2FMA(om23, p23, none2, one2);
            float o0, o1, o2, o3;
            F2UP(o0, o1, om01); F2UP(o2, o3, om23);
            F2PK(l01, __log2f(o0), __log2f(o1));
            F2PK(l23, __log2f(o2), __log2f(o3));
            F2FMA(acc01, pp01, l01, acc01);      // acc += p^2 * lg2(1-p)
            F2FMA(acc23, pp23, l23, acc23);
        }
        float a0, a1, a2, a3;
        F2UP(a0, a1, acc01); F2UP(a2, a3, acc23);
        float csum = KNEG * ((a0 + a1) + (a2 + a3));
        commit(csum, 0.0f, 0, b, s_c, s_r, s_p, out);
        return;
    }

    // ============ ASSIGN: f32x2-assisted IoU + exact ratio argmax + reg + correction ============
    const int b    = idx / NA_TILES;
    const int tile = idx - b * NA_TILES;

    if (t < NM) {
        float4 bx = ((const float4*)boxes)[b * NM + t];
        int lab   = labels[b * NM + t];
        if (lab == 0)                            // degenerate: inter clamps to 0
            bx = make_float4(3e9f, 3e9f, -3e9f, -3e9f);
        s_box[t] = bx;
        s_lab[t] = lab;
    }
    if (t < NP) {                                // pack pair q = t (boxes 2q, 2q+1)
        float4 e = ((const float4*)boxes)[b * NM + 2 * t];
        float4 o = ((const float4*)boxes)[b * NM + 2 * t + 1];
        int le = labels[b * NM + 2 * t], lo = labels[b * NM + 2 * t + 1];
        float bae, bao;
        if (le == 0) { e = make_float4(3e9f, 3e9f, -3e9f, -3e9f); bae = 0.0f; }
        else bae = (e.z - e.x) * (e.w - e.y);
        if (lo == 0) { o = make_float4(3e9f, 3e9f, -3e9f, -3e9f); bao = 0.0f; }
        else bao = (o.z - o.x) * (o.w - o.y);
        s_zx[t] = make_float4(e.z, o.z, -e.x, -o.x);
        s_wy[t] = make_float4(e.w, o.w, -e.y, -o.y);
        s_ba[t] = pk2c(bae, bao);
    }
    __syncthreads();

    const int a = tile * THREADS + t;
    float my_reg = 0.0f, my_cls = 0.0f;
    int   my_pos = 0;

    if (a < NA) {
        float4 an = ((const float4*)anchors)[a];   // y1,x1,y2,x2
        const float ay1 = an.x, ax1 = an.y, ay2 = an.z, ax2 = an.w;
        const float nax1 = -ax1, nay1 = -ay1;
        const float a_area = (ay2 - ay1) * (ax2 - ax1);
        u64 aar2; F2PK(aar2, a_area, a_area);

        // two argmax chains: lo = even boxes (2q), hi = odd (2q+1); exact cross-mult compare
        float bI0 = -1.0f, bS0 = 1.0f; int bq0 = 0;
        float bI1 = -1.0f, bS1 = 1.0f; int bq1 = 0;
        #pragma unroll 8
        for (int q = 0; q < NP; q++) {
            float4 zx = s_zx[q];                 // z_e,z_o,-x_e,-x_o
            float4 wy = s_wy[q];                 // w_e,w_o,-y_e,-y_o
            u64 ba = s_ba[q];
            u64 t1, t2, iw2, ih2, I2, S2;
            F2PK(t1, fminf(ax2,  zx.x), fminf(ax2,  zx.y));
            F2PK(t2, fminf(nax1, zx.z), fminf(nax1, zx.w));
            F2ADD(iw2, t1, t2);                  // min(ax2,z) - max(ax1,x), both lanes
            F2PK(t1, fminf(ay2,  wy.x), fminf(ay2,  wy.y));
            F2PK(t2, fminf(nay1, wy.z), fminf(nay1, wy.w));
            F2ADD(ih2, t1, t2);
            float iw0, iw1, ih0, ih1;
            F2UP(iw0, iw1, iw2); F2UP(ih0, ih1, ih2);
            u64 iwc, ihc;
            F2PK(iwc, fmaxf(iw0, 0.0f), fmaxf(iw1, 0.0f));
            F2PK(ihc, fmaxf(ih0, 0.0f), fmaxf(ih1, 0.0f));
            F2MUL(I2, iwc, ihc);
            F2ADD(S2, aar2, ba);
            float I0, I1, S0, S1;
            F2UP(I0, I1, I2); F2UP(S0, S1, S2);
            if (I0 * bS0 > bI0 * S0) { bI0 = I0; bS0 = S0; bq0 = q; }
            if (I1 * bS1 > bI1 * S1) { bI1 = I1; bS1 = S1; bq1 = q; }
        }
        // merge: odd chain wins only with STRICTLY larger ratio (first-max preserved)
        float bI = bI0, bS = bS0; int bidx = 2 * bq0;
        if (bI1 * bS0 > bI0 * bS1) { bI = bI1; bS = bS1; bidx = 2 * bq1 + 1; }

        float ua = fmaxf(bS - bI, 1e-8f);          // reference's exact ua
        float iou_max = bI / ua;                   // one IEEE divide per anchor

        float4 ab = s_box[bidx];
        float  bw = ab.z - ab.x, bh = ab.w - ab.y;
        bool   big = (bw * bh) > 100.0f;
        bool   pos = big ? (iou_max >= 0.5f) : (iou_max >= 0.15f);

        if (pos) {
            my_pos = 1;
            float gcx = ab.x + 0.5f * bw, gcy = ab.y + 0.5f * bh;
            float gw = fmaxf(bw, 1.0f), gh = fmaxf(bh, 1.0f);
            float aw = ax2 - ax1, ah = ay2 - ay1;
            float acx = ax1 + 0.5f * aw, acy = ay1 + 0.5f * ah;
            float tt0 = (gcy - acy) / ah;
            float tt1 = (gcx - acx) / aw;
            float tt2 = logf(gh / ah);
            float tt3 = logf(gw / aw);
            float4 r = ((const float4*)reg)[(size_t)b * NA + a];
            float d;
            d = fabsf(tt0 - r.x); my_reg += (d <= 1.0f/9.0f) ? 4.5f*d*d : d - 0.5f/9.0f;
            d = fabsf(tt1 - r.y); my_reg += (d <= 1.0f/9.0f) ? 4.5f*d*d : d - 0.5f/9.0f;
            d = fabsf(tt2 - r.z); my_reg += (d <= 1.0f/9.0f) ? 4.5f*d*d : d - 0.5f/9.0f;
            d = fabsf(tt3 - r.w); my_reg += (d <= 1.0f/9.0f) ? 4.5f*d*d : d - 0.5f/9.0f;

            // cls correction: + positive term, MINUS the neg term the stream added
            int al = s_lab[bidx] - 1;              // in [0, NC)
            float v = cls[((size_t)b * NA + a) * NC + al];
            float p = fminf(fmaxf(v, 1e-4f), 1.0f - 1e-4f);
            float om = 1.0f - p;
            float neg_term = KNEG * (p * p) * __log2f(om);   // what the stream added (>0)
            my_cls = 0.25f * om * om * (-__logf(p)) - neg_term;
        }
    }
    commit(my_cls, my_reg, my_pos, b, s_c, s_r, s_p, out);
}

extern "C" void kernel_launch(void* const* d_in, const int* in_sizes, int n_in,
                              void* d_out, int out_size) {
    const float* boxes   = (const float*)d_in[0];
    const int*   labels  = (const int*)  d_in[1];
    const float* anchors = (const float*)d_in[2];
    const float* cls     = (const float*)d_in[3];
    const float* reg     = (const float*)d_in[4];
    float* out = (float*)d_out;

    fl_kernel<<<TOTB, THREADS>>>(boxes, labels, anchors, cls, reg, out);
}